// round 2
// baseline (speedup 1.0000x reference)
#include <cuda_runtime.h>

#define Bq 512
#define Tq 128
#define Eq 256
#define Dq 256
#define G4 1024
#define NBLK 512

// ---------------- static device scratch ----------------
__device__ float g_pre[(size_t)Bq * Tq * Eq];   // enc @ W1_enc + b1  (64 MB)
__device__ float g_whhT[Dq * G4];               // w_hh transposed [k][j]
__device__ float g_bsum[G4];                    // b_ih + b_hh
__device__ float g_h[Bq * Dq];
__device__ float g_c[Bq * Dq];
__device__ float g_hp0[Bq * Eq];                // h @ W1_h
__device__ float g_hp1[Bq * Eq];                // c @ W1_c
__device__ float g_gp0[Bq * G4];                // h[:,0:128]   @ w_hhT[0:128,:]
__device__ float g_gp1[Bq * G4];                // h[:,128:256] @ w_hhT[128:256,:]
__device__ unsigned g_barcnt;
__device__ volatile unsigned g_bargen;

struct SmA { float As[16][68]; float Bs[16][64]; };
struct SmB { float hp[256]; float w2[256]; float sc[128]; float ctx[256]; float red[8]; float misc[4]; };
union Smem { SmA a; SmB b; };

__device__ __forceinline__ float tanh_fast(float x) {
    float e = __expf(2.0f * x);
    return 1.0f - __fdividef(2.0f, e + 1.0f);
}
__device__ __forceinline__ float sigmoid_f(float x) {
    return __fdividef(1.0f, 1.0f + __expf(-x));
}

// 64x64 output tile, K multiple of 16, 256 threads, 4x4 microtile.
__device__ __forceinline__ void gemm64x64(Smem* sm,
        const float* __restrict__ A, int lda,     // [64+][lda], rows from tile base
        const float* __restrict__ Bm, int ldb,    // [K][ldb], cols from tile base
        float* __restrict__ C, int ldc,
        int K, bool cgA, const float* __restrict__ bias)
{
    const int tid = threadIdx.x;
    const int tx = tid & 15, ty = tid >> 4;
    const int arow = tid >> 2, acol = (tid & 3) << 2;
    const int brow = tid >> 4, bcol = (tid & 15) << 2;

    float acc[4][4];
#pragma unroll
    for (int i = 0; i < 4; i++)
#pragma unroll
        for (int j = 0; j < 4; j++) acc[i][j] = 0.f;

    for (int k0 = 0; k0 < K; k0 += 16) {
        const float* Ap = A + (size_t)arow * lda + (k0 + acol);
        float4 av = cgA ? __ldcg((const float4*)Ap) : *(const float4*)Ap;
        float4 bv = *(const float4*)(Bm + (size_t)(k0 + brow) * ldb + bcol);

        sm->a.As[acol + 0][arow] = av.x;
        sm->a.As[acol + 1][arow] = av.y;
        sm->a.As[acol + 2][arow] = av.z;
        sm->a.As[acol + 3][arow] = av.w;
        *(float4*)&sm->a.Bs[brow][bcol] = bv;
        __syncthreads();

#pragma unroll
        for (int k = 0; k < 16; k++) {
            float4 aq = *(const float4*)&sm->a.As[k][ty << 2];
            float4 bq = *(const float4*)&sm->a.Bs[k][tx << 2];
            float a4[4] = {aq.x, aq.y, aq.z, aq.w};
            float b4[4] = {bq.x, bq.y, bq.z, bq.w};
#pragma unroll
            for (int i = 0; i < 4; i++)
#pragma unroll
                for (int j = 0; j < 4; j++)
                    acc[i][j] = fmaf(a4[i], b4[j], acc[i][j]);
        }
        __syncthreads();
    }

#pragma unroll
    for (int i = 0; i < 4; i++)
#pragma unroll
        for (int j = 0; j < 4; j++) {
            float v = acc[i][j];
            if (bias) v += bias[(tx << 2) + j];
            C[(size_t)((ty << 2) + i) * ldc + (tx << 2) + j] = v;
        }
}

__device__ __forceinline__ void gridbar() {
    __syncthreads();
    if (threadIdx.x == 0) {
        __threadfence();
        unsigned gen = g_bargen;
        if (atomicAdd(&g_barcnt, 1u) == NBLK - 1u) {
            g_barcnt = 0u;
            __threadfence();
            g_bargen = gen + 1u;
        } else {
            while (g_bargen == gen) __nanosleep(64);
        }
        __threadfence();
    }
    __syncthreads();
}

__device__ __forceinline__ void phaseB(Smem& sm, int b, int t,
        const float* __restrict__ enc, const float* __restrict__ yhist,
        const float* __restrict__ attn_w2, const float* __restrict__ w_ih,
        const float* __restrict__ fc_w, const float* __restrict__ fc_b,
        const float* __restrict__ fcf_w, const float* __restrict__ fcf_b,
        float* __restrict__ out)
{
    const int tid = threadIdx.x;
    const int lane = tid & 31, warp = tid >> 5;

    sm.b.hp[tid] = __ldcg(&g_hp0[b * Eq + tid]) + __ldcg(&g_hp1[b * Eq + tid]);
    sm.b.w2[tid] = attn_w2[tid];
    __syncthreads();

    // scores: warp per t (8 warps -> 16 t's each)
    const float* preb = g_pre + (size_t)b * Tq * Eq;
    for (int tt = warp; tt < Tq; tt += 8) {
        const float* pr = preb + (size_t)tt * Eq;
        float acc = 0.f;
#pragma unroll
        for (int i = 0; i < 8; i++) {
            int e = lane + (i << 5);
            acc += sm.b.w2[e] * tanh_fast(pr[e] + sm.b.hp[e]);
        }
#pragma unroll
        for (int o = 16; o; o >>= 1) acc += __shfl_xor_sync(0xffffffffu, acc, o);
        if (lane == 0) sm.b.sc[tt] = acc;
    }
    __syncthreads();

    // softmax over T=128 (b2 dropped: shift-invariant)
    float s = (tid < Tq) ? sm.b.sc[tid] : -3.0e38f;
    float m = s;
#pragma unroll
    for (int o = 16; o; o >>= 1) m = fmaxf(m, __shfl_xor_sync(0xffffffffu, m, o));
    if (lane == 0) sm.b.red[warp] = m;
    __syncthreads();
    if (tid == 0) {
        float mm = sm.b.red[0];
#pragma unroll
        for (int w = 1; w < 8; w++) mm = fmaxf(mm, sm.b.red[w]);
        sm.b.misc[0] = mm;
    }
    __syncthreads();
    float ex = (tid < Tq) ? __expf(s - sm.b.misc[0]) : 0.f;
    float ssum = ex;
#pragma unroll
    for (int o = 16; o; o >>= 1) ssum += __shfl_xor_sync(0xffffffffu, ssum, o);
    if (lane == 0) sm.b.red[warp] = ssum;
    __syncthreads();
    if (tid == 0) {
        float tot = 0.f;
#pragma unroll
        for (int w = 0; w < 8; w++) tot += sm.b.red[w];
        sm.b.misc[1] = __fdividef(1.0f, tot);
    }
    if (tid < Tq) sm.b.sc[tid] = ex;
    __syncthreads();
    float invs = sm.b.misc[1];

    // ctx[e] = invs * sum_t ex[t] * enc[b,t,e]   (thread = e)
    const float* encb = enc + (size_t)b * Tq * Eq + tid;
    float ca = 0.f;
#pragma unroll 8
    for (int tt = 0; tt < Tq; tt++)
        ca = fmaf(sm.b.sc[tt], encb[(size_t)tt * Eq], ca);
    ca *= invs;
    sm.b.ctx[tid] = ca;

    // y_tilde = ctx . fc_w[0:256] + y_t*fc_w[256] + fc_b
    float ps = ca * fc_w[tid];
#pragma unroll
    for (int o = 16; o; o >>= 1) ps += __shfl_xor_sync(0xffffffffu, ps, o);
    __syncthreads();
    if (lane == 0) sm.b.red[warp] = ps;
    __syncthreads();
    if (tid == 0) {
        float tot = 0.f;
#pragma unroll
        for (int w = 0; w < 8; w++) tot += sm.b.red[w];
        sm.b.misc[2] = tot + yhist[b * Tq + t] * fc_w[256] + fc_b[0];
    }
    __syncthreads();
    float yt = sm.b.misc[2];

    // gates (i,f,g,o) & LSTM update, thread = d
    int d = tid;
    float gi = fmaf(yt, w_ih[d],       g_bsum[d])       + __ldcg(&g_gp0[b * G4 + d])       + __ldcg(&g_gp1[b * G4 + d]);
    float gf = fmaf(yt, w_ih[256 + d], g_bsum[256 + d]) + __ldcg(&g_gp0[b * G4 + 256 + d]) + __ldcg(&g_gp1[b * G4 + 256 + d]);
    float gg = fmaf(yt, w_ih[512 + d], g_bsum[512 + d]) + __ldcg(&g_gp0[b * G4 + 512 + d]) + __ldcg(&g_gp1[b * G4 + 512 + d]);
    float go = fmaf(yt, w_ih[768 + d], g_bsum[768 + d]) + __ldcg(&g_gp0[b * G4 + 768 + d]) + __ldcg(&g_gp1[b * G4 + 768 + d]);
    float cprev = __ldcg(&g_c[b * Dq + d]);
    float cn = sigmoid_f(gf) * cprev + sigmoid_f(gi) * tanhf(gg);
    float hn = sigmoid_f(go) * tanhf(cn);
    g_c[b * Dq + d] = cn;
    g_h[b * Dq + d] = hn;

    if (t == Tq - 1) {
        // out[b] = [h|ctx] . fcf_w + fcf_b
        float q = hn * fcf_w[d] + sm.b.ctx[d] * fcf_w[Dq + d];
#pragma unroll
        for (int o = 16; o; o >>= 1) q += __shfl_xor_sync(0xffffffffu, q, o);
        __syncthreads();
        if (lane == 0) sm.b.red[warp] = q;
        __syncthreads();
        if (tid == 0) {
            float tot = 0.f;
#pragma unroll
            for (int w = 0; w < 8; w++) tot += sm.b.red[w];
            out[b] = tot + fcf_b[0];
        }
    }
}

__global__ void __launch_bounds__(256, 4) decoder_persist(
        const float* __restrict__ enc, const float* __restrict__ yhist,
        const float* __restrict__ attn_w1, const float* __restrict__ attn_w2,
        const float* __restrict__ w_ih,
        const float* __restrict__ fc_w, const float* __restrict__ fc_b,
        const float* __restrict__ fcf_w, const float* __restrict__ fcf_b,
        float* __restrict__ out)
{
    __shared__ Smem sm;
    const int bid = blockIdx.x;

    for (int t = 0; t < Tq; t++) {
        // ---- phase A: step GEMMs (320 tiles) ----
        if (bid < 320) {
            if (bid < 64) {
                // hp_p = (p==0 ? h : c) @ W1_p   [512,256] x [256,256]
                int p = bid >> 5, r = bid & 31;
                int mt = r >> 2, nt = r & 3;
                const float* A = (p == 0 ? g_h : g_c) + mt * 64 * Dq;
                const float* Bm = attn_w1 + (size_t)p * 256 * Eq + nt * 64;
                float* C = (p == 0 ? g_hp0 : g_hp1) + mt * 64 * Eq + nt * 64;
                gemm64x64(&sm, A, Dq, Bm, Eq, C, Eq, 256, true, nullptr);
            } else {
                // gp_p = h[:, p*128:(p+1)*128] @ whhT[p*128:(p+1)*128, :]
                int idx = bid - 64;
                int p = idx >> 7, r = idx & 127;
                int mt = r >> 4, nt = r & 15;
                const float* A = g_h + mt * 64 * Dq + p * 128;
                const float* Bm = g_whhT + (size_t)p * 128 * G4 + nt * 64;
                float* C = (p == 0 ? g_gp0 : g_gp1) + mt * 64 * G4 + nt * 64;
                gemm64x64(&sm, A, Dq, Bm, G4, C, G4, 128, true, nullptr);
            }
        }
        gridbar();
        // ---- phase B: attention + LSTM for batch row b = bid ----
        phaseB(sm, bid, t, enc, yhist, attn_w2, w_ih, fc_w, fc_b, fcf_w, fcf_b, out);
        gridbar();
    }
}

__global__ void prep_kernel(const float* __restrict__ w_hh,
                            const float* __restrict__ b_ih,
                            const float* __restrict__ b_hh)
{
    int i = blockIdx.x * blockDim.x + threadIdx.x;
    if (i < G4 * Dq) {
        int j = i >> 8;      // gate row 0..1023
        int k = i & 255;     // hidden dim
        g_whhT[(size_t)k * G4 + j] = w_hh[i];
    }
    if (i < G4) g_bsum[i] = b_ih[i] + b_hh[i];
    if (i < Bq * Dq) { g_h[i] = 0.f; g_c[i] = 0.f; }
    if (i == 0) { g_barcnt = 0u; g_bargen = 0u; }
}

__global__ void __launch_bounds__(256) pre_gemm_kernel(
        const float* __restrict__ enc, const float* __restrict__ attn_w1,
        const float* __restrict__ attn_b1)
{
    __shared__ Smem sm;
    int mt = blockIdx.x >> 2, nt = blockIdx.x & 3;
    const float* A = enc + (size_t)mt * 64 * Eq;
    const float* Bm = attn_w1 + (size_t)512 * Eq + nt * 64;
    float* C = g_pre + (size_t)mt * 64 * Eq + nt * 64;
    gemm64x64(&sm, A, Eq, Bm, Eq, C, Eq, 256, false, attn_b1 + nt * 64);
}

extern "C" void kernel_launch(void* const* d_in, const int* in_sizes, int n_in,
                              void* d_out, int out_size)
{
    const float* enc     = (const float*)d_in[0];
    const float* yhist   = (const float*)d_in[1];
    const float* attn_w1 = (const float*)d_in[2];
    const float* attn_b1 = (const float*)d_in[3];
    const float* attn_w2 = (const float*)d_in[4];
    // d_in[5] = attn_b2: unused (softmax is shift-invariant)
    const float* w_ih    = (const float*)d_in[6];
    const float* w_hh    = (const float*)d_in[7];
    const float* b_ih    = (const float*)d_in[8];
    const float* b_hh    = (const float*)d_in[9];
    const float* fc_w    = (const float*)d_in[10];
    const float* fc_b    = (const float*)d_in[11];
    const float* fcf_w   = (const float*)d_in[12];
    const float* fcf_b   = (const float*)d_in[13];
    float* out = (float*)d_out;

    prep_kernel<<<1024, 256>>>(w_hh, b_ih, b_hh);
    pre_gemm_kernel<<<(Bq * Tq / 64) * 4, 256>>>(enc, attn_w1, attn_b1);
    decoder_persist<<<NBLK, 256>>>(enc, yhist, attn_w1, attn_w2, w_ih,
                                   fc_w, fc_b, fcf_w, fcf_b, out);
}

// round 3
// speedup vs baseline: 1.0230x; 1.0230x over previous
#include <cuda_runtime.h>
#include <cuda_fp16.h>

#define Bq 512
#define Tq 128
#define Eq 256
#define Dq 256
#define G4 1024
#define NBLK 512

// ---------------- static device scratch ----------------
__device__ __half g_pre[(size_t)Bq * Tq * Eq];   // enc @ W1_enc + b1  (fp16, 32 MB)
__device__ float g_whhT[Dq * G4];                // w_hh transposed [k][j]
__device__ float g_bsum[G4];                     // b_ih + b_hh
__device__ float g_h[Bq * Dq];
__device__ float g_c[Bq * Dq];
__device__ float g_hp[8 * Bq * Eq];              // 8 partials of [h|c]@W1_hc (4 MB)
__device__ float g_gp[4 * (size_t)Bq * G4];      // 4 K-partials of h@w_hhT (8 MB)
__device__ unsigned g_barcnt;
__device__ volatile unsigned g_bargen;

struct SmA { float As[16][68]; float Bs[16][64]; };
struct SmB {
    float hp[256]; float sc[128];
    float ctxp[4][256]; float ctx[256];
    float red[8]; float misc[4];
};
union Smem { SmA a; SmB b; };

__device__ __forceinline__ float tanh_fast(float x) {
    float e = __expf(2.0f * x);
    return 1.0f - __fdividef(2.0f, e + 1.0f);
}
__device__ __forceinline__ float sigmoid_f(float x) {
    return __fdividef(1.0f, 1.0f + __expf(-x));
}

// 64x64 output tile, K multiple of 16, 256 threads, 4x4 microtile.
template<typename TO>
__device__ __forceinline__ void gemm64x64(SmA* sm,
        const float* __restrict__ A, int lda,
        const float* __restrict__ Bm, int ldb,
        TO* __restrict__ C, int ldc,
        int K, const float* __restrict__ bias)
{
    const int tid = threadIdx.x;
    const int tx = tid & 15, ty = tid >> 4;
    const int arow = tid >> 2, acol = (tid & 3) << 2;
    const int brow = tid >> 4, bcol = (tid & 15) << 2;

    float acc[4][4];
#pragma unroll
    for (int i = 0; i < 4; i++)
#pragma unroll
        for (int j = 0; j < 4; j++) acc[i][j] = 0.f;

    for (int k0 = 0; k0 < K; k0 += 16) {
        float4 av = __ldcg((const float4*)(A + (size_t)arow * lda + (k0 + acol)));
        float4 bv = *(const float4*)(Bm + (size_t)(k0 + brow) * ldb + bcol);

        sm->As[acol + 0][arow] = av.x;
        sm->As[acol + 1][arow] = av.y;
        sm->As[acol + 2][arow] = av.z;
        sm->As[acol + 3][arow] = av.w;
        *(float4*)&sm->Bs[brow][bcol] = bv;
        __syncthreads();

#pragma unroll
        for (int k = 0; k < 16; k++) {
            float4 aq = *(const float4*)&sm->As[k][ty << 2];
            float4 bq = *(const float4*)&sm->Bs[k][tx << 2];
            float a4[4] = {aq.x, aq.y, aq.z, aq.w};
            float b4[4] = {bq.x, bq.y, bq.z, bq.w};
#pragma unroll
            for (int i = 0; i < 4; i++)
#pragma unroll
                for (int j = 0; j < 4; j++)
                    acc[i][j] = fmaf(a4[i], b4[j], acc[i][j]);
        }
        __syncthreads();
    }

#pragma unroll
    for (int i = 0; i < 4; i++)
#pragma unroll
        for (int j = 0; j < 4; j++) {
            float v = acc[i][j];
            if (bias) v += bias[(tx << 2) + j];
            C[(size_t)((ty << 2) + i) * ldc + (tx << 2) + j] = (TO)v;
        }
}

__device__ __forceinline__ void gridbar() {
    __syncthreads();
    if (threadIdx.x == 0) {
        __threadfence();
        unsigned gen = g_bargen;
        if (atomicAdd(&g_barcnt, 1u) == NBLK - 1u) {
            g_barcnt = 0u;
            __threadfence();
            g_bargen = gen + 1u;
        } else {
            while (g_bargen == gen) __nanosleep(32);
        }
        __threadfence();
    }
    __syncthreads();
}

__global__ void __launch_bounds__(256, 4) decoder_persist(
        const float* __restrict__ enc, const float* __restrict__ yhist,
        const float* __restrict__ attn_w1, const float* __restrict__ attn_w2,
        const float* __restrict__ w_ih,
        const float* __restrict__ fc_w, const float* __restrict__ fc_b,
        const float* __restrict__ fcf_w, const float* __restrict__ fcf_b,
        float* __restrict__ out)
{
    __shared__ Smem sm;
    const int bid = blockIdx.x;
    const int tid = threadIdx.x;
    const int lane = tid & 31, warp = tid >> 5;
    const int b = bid;

    for (int t = 0; t < Tq; t++) {
        // ---------- R1: hp partials (256 units, 64x64xK64 each) ----------
        if (bid < 256) {
            int src = bid >> 7, r = bid & 127;
            int kq = r >> 5, rr = r & 31, mt = rr >> 2, nt = rr & 3;
            const float* A = (src ? g_c : g_h) + mt * 64 * Dq + kq * 64;
            const float* Bm = attn_w1 + (size_t)(src * 256 + kq * 64) * Eq + nt * 64;
            float* C = g_hp + (src * 4 + kq) * (Bq * Eq) + mt * 64 * Eq + nt * 64;
            gemm64x64(&sm.a, A, Dq, Bm, Eq, C, Eq, 64, (const float*)0);
        }
        gridbar();

        // ---------- R2: gp GEMM unit (all 512 blocks) then attention ----------
        {
            int kq = bid >> 7, r = bid & 127, mt = r >> 4, nt = r & 15;
            const float* A = g_h + mt * 64 * Dq + kq * 64;
            const float* Bm = g_whhT + (size_t)(kq * 64) * G4 + nt * 64;
            float* C = g_gp + (size_t)kq * (Bq * G4) + mt * 64 * G4 + nt * 64;
            gemm64x64(&sm.a, A, Dq, Bm, G4, C, G4, 64, (const float*)0);
        }
        __syncthreads();

        // attention for batch row b = bid
        {
            float hpv = 0.f;
#pragma unroll
            for (int q = 0; q < 8; q++)
                hpv += __ldcg(&g_hp[q * (Bq * Eq) + b * Eq + tid]);
            sm.b.hp[tid] = hpv;
            __syncthreads();

            float hpr[8], w2r[8];
            const int e0 = lane * 8;
#pragma unroll
            for (int j = 0; j < 8; j++) {
                hpr[j] = sm.b.hp[e0 + j];
                w2r[j] = attn_w2[e0 + j];
            }

            // scores: warp per t; one LDG.128 covers 8 fp16 per lane = full E row
            const uint4* preb = (const uint4*)(g_pre + (size_t)b * Tq * Eq);
            for (int tt = warp; tt < Tq; tt += 8) {
                uint4 pv = __ldcg(preb + tt * 32 + lane);
                const __half2* ph = (const __half2*)&pv;
                float acc = 0.f;
#pragma unroll
                for (int j = 0; j < 4; j++) {
                    float2 f = __half22float2(ph[j]);
                    acc = fmaf(w2r[2 * j],     tanh_fast(hpr[2 * j] + f.x),     acc);
                    acc = fmaf(w2r[2 * j + 1], tanh_fast(hpr[2 * j + 1] + f.y), acc);
                }
#pragma unroll
                for (int o = 16; o; o >>= 1) acc += __shfl_xor_sync(0xffffffffu, acc, o);
                if (lane == 0) sm.b.sc[tt] = acc;
            }
            __syncthreads();

            // softmax over T=128 (attn_b2 dropped: shift-invariant)
            float s = (tid < Tq) ? sm.b.sc[tid] : -3.0e38f;
            float m = s;
#pragma unroll
            for (int o = 16; o; o >>= 1) m = fmaxf(m, __shfl_xor_sync(0xffffffffu, m, o));
            if (lane == 0) sm.b.red[warp] = m;
            __syncthreads();
            if (tid == 0) {
                float mm = sm.b.red[0];
#pragma unroll
                for (int w = 1; w < 8; w++) mm = fmaxf(mm, sm.b.red[w]);
                sm.b.misc[0] = mm;
            }
            __syncthreads();
            float ex = (tid < Tq) ? __expf(s - sm.b.misc[0]) : 0.f;
            float ssum = ex;
#pragma unroll
            for (int o = 16; o; o >>= 1) ssum += __shfl_xor_sync(0xffffffffu, ssum, o);
            if (lane == 0) sm.b.red[warp] = ssum;
            __syncthreads();
            if (tid == 0) {
                float tot = 0.f;
#pragma unroll
                for (int w = 0; w < 8; w++) tot += sm.b.red[w];
                sm.b.misc[1] = __fdividef(1.0f, tot);
            }
            if (tid < Tq) sm.b.sc[tid] = ex;
            __syncthreads();
            float invs = sm.b.misc[1];

            // ctx: t-quartered, float4 over e
            {
                int qt = tid >> 6, ec = tid & 63;
                const float4* enc4 = (const float4*)(enc + (size_t)b * Tq * Eq);
                float4 ca = make_float4(0.f, 0.f, 0.f, 0.f);
                int t0 = qt * 32;
#pragma unroll 4
                for (int tt = t0; tt < t0 + 32; tt++) {
                    float w = sm.b.sc[tt];
                    float4 ev = __ldcg(enc4 + (size_t)tt * 64 + ec);
                    ca.x = fmaf(w, ev.x, ca.x);
                    ca.y = fmaf(w, ev.y, ca.y);
                    ca.z = fmaf(w, ev.z, ca.z);
                    ca.w = fmaf(w, ev.w, ca.w);
                }
                *(float4*)&sm.b.ctxp[qt][ec << 2] = ca;
            }
            __syncthreads();
            float cv = (sm.b.ctxp[0][tid] + sm.b.ctxp[1][tid] +
                        sm.b.ctxp[2][tid] + sm.b.ctxp[3][tid]) * invs;
            sm.b.ctx[tid] = cv;

            // y_tilde = ctx . fc_w[0:256] + y_t*fc_w[256] + fc_b
            float ps = cv * fc_w[tid];
#pragma unroll
            for (int o = 16; o; o >>= 1) ps += __shfl_xor_sync(0xffffffffu, ps, o);
            __syncthreads();
            if (lane == 0) sm.b.red[warp] = ps;
            __syncthreads();
            if (tid == 0) {
                float tot = 0.f;
#pragma unroll
                for (int w = 0; w < 8; w++) tot += sm.b.red[w];
                sm.b.misc[2] = tot + yhist[b * Tq + t] * fc_w[256] + fc_b[0];
            }
        }
        gridbar();

        // ---------- R3: LSTM epilogue for row b ----------
        {
            float yt = sm.b.misc[2];
            int d = tid;
            float gv[4];
#pragma unroll
            for (int g = 0; g < 4; g++) {
                float a = fmaf(yt, w_ih[g * 256 + d], g_bsum[g * 256 + d]);
#pragma unroll
                for (int kq = 0; kq < 4; kq++)
                    a += __ldcg(&g_gp[(size_t)kq * (Bq * G4) + (size_t)b * G4 + g * 256 + d]);
                gv[g] = a;
            }
            float cprev = g_c[b * Dq + d];
            float cn = sigmoid_f(gv[1]) * cprev + sigmoid_f(gv[0]) * tanhf(gv[2]);
            float hn = sigmoid_f(gv[3]) * tanhf(cn);
            g_c[b * Dq + d] = cn;
            g_h[b * Dq + d] = hn;

            if (t == Tq - 1) {
                float q = hn * fcf_w[d] + sm.b.ctx[d] * fcf_w[Dq + d];
#pragma unroll
                for (int o = 16; o; o >>= 1) q += __shfl_xor_sync(0xffffffffu, q, o);
                __syncthreads();
                if (lane == 0) sm.b.red[warp] = q;
                __syncthreads();
                if (tid == 0) {
                    float tot = 0.f;
#pragma unroll
                    for (int w = 0; w < 8; w++) tot += sm.b.red[w];
                    out[b] = tot + fcf_b[0];
                }
            }
        }
        gridbar();
    }
}

__global__ void prep_kernel(const float* __restrict__ w_hh,
                            const float* __restrict__ b_ih,
                            const float* __restrict__ b_hh)
{
    int i = blockIdx.x * blockDim.x + threadIdx.x;
    if (i < G4 * Dq) {
        int j = i >> 8;      // gate row 0..1023
        int k = i & 255;     // hidden dim
        g_whhT[(size_t)k * G4 + j] = w_hh[i];
    }
    if (i < G4) g_bsum[i] = b_ih[i] + b_hh[i];
    if (i < Bq * Dq) { g_h[i] = 0.f; g_c[i] = 0.f; }
    if (i == 0) { g_barcnt = 0u; g_bargen = 0u; }
}

__global__ void __launch_bounds__(256) pre_gemm_kernel(
        const float* __restrict__ enc, const float* __restrict__ attn_w1,
        const float* __restrict__ attn_b1)
{
    __shared__ SmA sa;
    int mt = blockIdx.x >> 2, nt = blockIdx.x & 3;   // 1024 row-tiles x 4 col-tiles
    const float* A = enc + (size_t)mt * 64 * Eq;
    const float* Bm = attn_w1 + (size_t)(2 * Dq) * Eq + nt * 64;
    __half* C = g_pre + (size_t)mt * 64 * Eq + nt * 64;
    gemm64x64(&sa, A, Eq, Bm, Eq, C, Eq, 256, attn_b1 + nt * 64);
}

extern "C" void kernel_launch(void* const* d_in, const int* in_sizes, int n_in,
                              void* d_out, int out_size)
{
    const float* enc     = (const float*)d_in[0];
    const float* yhist   = (const float*)d_in[1];
    const float* attn_w1 = (const float*)d_in[2];
    const float* attn_b1 = (const float*)d_in[3];
    const float* attn_w2 = (const float*)d_in[4];
    // d_in[5] = attn_b2: unused (softmax is shift-invariant)
    const float* w_ih    = (const float*)d_in[6];
    const float* w_hh    = (const float*)d_in[7];
    const float* b_ih    = (const float*)d_in[8];
    const float* b_hh    = (const float*)d_in[9];
    const float* fc_w    = (const float*)d_in[10];
    const float* fc_b    = (const float*)d_in[11];
    const float* fcf_w   = (const float*)d_in[12];
    const float* fcf_b   = (const float*)d_in[13];
    float* out = (float*)d_out;

    prep_kernel<<<1024, 256>>>(w_hh, b_ih, b_hh);
    pre_gemm_kernel<<<4096, 256>>>(enc, attn_w1, attn_b1);
    decoder_persist<<<NBLK, 256>>>(enc, yhist, attn_w1, attn_w2, w_ih,
                                   fc_w, fc_b, fcf_w, fcf_b, out);
}

// round 4
// speedup vs baseline: 1.4703x; 1.4372x over previous
#include <cuda_runtime.h>
#include <cuda_fp16.h>

#define Bq 512
#define Tq 128
#define Eq 256
#define Dq 256
#define G4 1024
#define BT (Bq*Tq)
#define NBLK 512
#define NLEAF 16
#define PER_LEAF (NBLK/NLEAF)

// ---------------- static device scratch ----------------
__device__ __half g_pre[(size_t)BT * Eq];     // enc @ W1_enc + b1 (fp16, 32MB)
__device__ __half g_encH[(size_t)BT * Eq];    // fp16 copy of enc (32MB)
__device__ float g_whhT[Dq * G4];             // w_hh transposed [k][gate*256+d]
__device__ float g_bsum[G4];                  // b_ih + b_hh
__device__ float g_h[Bq * Dq];
__device__ float g_c[Bq * Dq];
__device__ float g_hp[16 * Bq * Eq];          // 16 K-partials of [h|c]@W1_hc
__device__ float g_gp[8 * (size_t)Bq * G4];   // 8 K-partials of h@w_hhT
__device__ unsigned g_cnt[NLEAF * 32];        // leaf counters (spread 128B apart)
__device__ unsigned g_master;
__device__ volatile unsigned g_gen;

struct SmA { float As[16][136]; float Bs[16][68]; };
struct SmB {
    float hp[256]; float sc[128]; float ctxp[8][256];
    float ctx[256]; float red[8]; float misc[4];
};
union Smem { SmA a; SmB b; };

__device__ __forceinline__ float tanh_approx(float x) {
    float y; asm("tanh.approx.f32 %0, %1;" : "=f"(y) : "f"(x)); return y;
}
__device__ __forceinline__ float sigmoid_f(float x) {
    return __fdividef(1.0f, 1.0f + __expf(-x));
}

// 128x64 output tile, K multiple of 16, 256 threads, 8x4 microtile.
template<typename TO>
__device__ __forceinline__ void gemm128x64(SmA* s,
        const float* __restrict__ A, int lda,
        const float* __restrict__ Bm, int ldb,
        TO* __restrict__ C, int ldc, int K,
        const float* __restrict__ bias)
{
    const int tid = threadIdx.x;
    const int ty = tid >> 4, tx = tid & 15;
    const int arow = tid >> 2, ac4 = (tid & 3) << 2;
    const int bk = tid >> 4, bc4 = (tid & 15) << 2;

    float acc[8][4];
#pragma unroll
    for (int i = 0; i < 8; i++)
#pragma unroll
        for (int j = 0; j < 4; j++) acc[i][j] = 0.f;

    for (int k0 = 0; k0 < K; k0 += 16) {
        float4 av0 = __ldcg((const float4*)(A + (size_t)arow * lda + k0 + ac4));
        float4 av1 = __ldcg((const float4*)(A + (size_t)(arow + 64) * lda + k0 + ac4));
        float4 bv  = __ldcg((const float4*)(Bm + (size_t)(k0 + bk) * ldb + bc4));
        s->As[ac4 + 0][arow] = av0.x; s->As[ac4 + 1][arow] = av0.y;
        s->As[ac4 + 2][arow] = av0.z; s->As[ac4 + 3][arow] = av0.w;
        s->As[ac4 + 0][arow + 64] = av1.x; s->As[ac4 + 1][arow + 64] = av1.y;
        s->As[ac4 + 2][arow + 64] = av1.z; s->As[ac4 + 3][arow + 64] = av1.w;
        *(float4*)&s->Bs[bk][bc4] = bv;
        __syncthreads();
#pragma unroll
        for (int k = 0; k < 16; k++) {
            float4 a0 = *(const float4*)&s->As[k][ty << 3];
            float4 a1 = *(const float4*)&s->As[k][(ty << 3) + 4];
            float4 b4 = *(const float4*)&s->Bs[k][tx << 2];
            float av[8] = {a0.x, a0.y, a0.z, a0.w, a1.x, a1.y, a1.z, a1.w};
            float bb[4] = {b4.x, b4.y, b4.z, b4.w};
#pragma unroll
            for (int i = 0; i < 8; i++)
#pragma unroll
                for (int j = 0; j < 4; j++)
                    acc[i][j] = fmaf(av[i], bb[j], acc[i][j]);
        }
        __syncthreads();
    }
#pragma unroll
    for (int i = 0; i < 8; i++) {
        float v0 = acc[i][0], v1 = acc[i][1], v2 = acc[i][2], v3 = acc[i][3];
        if (bias) {
            v0 += bias[(tx << 2) + 0]; v1 += bias[(tx << 2) + 1];
            v2 += bias[(tx << 2) + 2]; v3 += bias[(tx << 2) + 3];
        }
        size_t off = (size_t)((ty << 3) + i) * ldc + (tx << 2);
        if constexpr (sizeof(TO) == 2) {
            __half2 h0 = __floats2half2_rn(v0, v1);
            __half2 h1 = __floats2half2_rn(v2, v3);
            uint2 u; u.x = *(unsigned*)&h0; u.y = *(unsigned*)&h1;
            *(uint2*)((__half*)C + off) = u;
        } else {
            *(float4*)((float*)C + off) = make_float4(v0, v1, v2, v3);
        }
    }
}

__device__ __forceinline__ void gridbar() {
    __threadfence();
    __syncthreads();
    if (threadIdx.x == 0) {
        unsigned gen = g_gen;
        unsigned leaf = (blockIdx.x & (NLEAF - 1)) * 32;
        unsigned v = atomicAdd(&g_cnt[leaf], 1u) + 1u;
        if (v == (gen + 1u) * PER_LEAF) {
            unsigned m = atomicAdd(&g_master, 1u) + 1u;
            if (m == (gen + 1u) * NLEAF) {
                g_gen = gen + 1u;
            } else {
                while (g_gen == gen) __nanosleep(32);
            }
        } else {
            while (g_gen == gen) __nanosleep(64);
        }
        __threadfence();
    }
    __syncthreads();
}

__global__ void __launch_bounds__(256, 4) decoder_persist(
        const float* __restrict__ yhist,
        const float* __restrict__ attn_w1, const float* __restrict__ attn_w2,
        const float* __restrict__ w_ih,
        const float* __restrict__ fc_w, const float* __restrict__ fc_b,
        const float* __restrict__ fcf_w, const float* __restrict__ fcf_b,
        float* __restrict__ out)
{
    __shared__ Smem sm;
    const int bid = blockIdx.x;
    const int tid = threadIdx.x;
    const int lane = tid & 31, warp = tid >> 5;
    const int b = bid;

    for (int t = 0; t < Tq; t++) {
        // ============ phase 1: all step-GEMM partials ============
        {   // gp unit = bid : h @ w_hhT, tile 128x64, K-chunk 32
            int tile = bid >> 3, kq = bid & 7;
            int mt = tile >> 4, nt = tile & 15;
            gemm128x64<float>(&sm.a,
                g_h + (size_t)mt * 128 * Dq + kq * 32, Dq,
                g_whhT + (size_t)(kq * 32) * G4 + nt * 64, G4,
                g_gp + (size_t)kq * (Bq * G4) + (size_t)mt * 128 * G4 + nt * 64, G4,
                32, (const float*)0);
        }
        if ((bid & 1) == 0) {   // hp unit = bid>>1 : [h|c] @ W1_hc
            int u = bid >> 1;
            int tile = u >> 4, kq = u & 15;
            int mt = tile >> 2, nt = tile & 3;
            const float* A = (kq < 8 ? g_h + kq * 32 : g_c + (kq - 8) * 32)
                             + (size_t)mt * 128 * Dq;
            gemm128x64<float>(&sm.a, A, Dq,
                attn_w1 + (size_t)(kq * 32) * Eq + nt * 64, Eq,
                g_hp + (size_t)kq * (Bq * Eq) + (size_t)mt * 128 * Eq + nt * 64, Eq,
                32, (const float*)0);
        }
        gridbar();

        // ============ phase 2: attention + LSTM, all row-local (row b = bid) ============
        {
            float hpv = 0.f;
#pragma unroll
            for (int q = 0; q < 16; q++)
                hpv += __ldcg(&g_hp[(size_t)q * (Bq * Eq) + b * Eq + tid]);
            sm.b.hp[tid] = hpv;
            __syncthreads();

            float hpr[8], w2r[8];
#pragma unroll
            for (int j = 0; j < 8; j++) {
                hpr[j] = sm.b.hp[lane * 8 + j];
                w2r[j] = attn_w2[lane * 8 + j];
            }

            // scores: warp handles 16 t's, 4 loads in flight
            const uint4* preb = (const uint4*)(g_pre + (size_t)b * Tq * Eq);
#pragma unroll
            for (int tb = 0; tb < 4; tb++) {
                int tt0 = warp + tb * 32;
                uint4 pv[4];
#pragma unroll
                for (int j = 0; j < 4; j++)
                    pv[j] = __ldcg(preb + (size_t)(tt0 + j * 8) * 32 + lane);
#pragma unroll
                for (int j = 0; j < 4; j++) {
                    const __half2* ph = (const __half2*)&pv[j];
                    float a = 0.f;
#pragma unroll
                    for (int q = 0; q < 4; q++) {
                        float2 f = __half22float2(ph[q]);
                        a = fmaf(w2r[2 * q],     tanh_approx(hpr[2 * q]     + f.x), a);
                        a = fmaf(w2r[2 * q + 1], tanh_approx(hpr[2 * q + 1] + f.y), a);
                    }
#pragma unroll
                    for (int o = 16; o; o >>= 1) a += __shfl_xor_sync(0xffffffffu, a, o);
                    if (lane == 0) sm.b.sc[tt0 + j * 8] = a;
                }
            }
            __syncthreads();

            // softmax over T=128 (attn_b2 dropped: shift-invariant)
            float sv = (tid < Tq) ? sm.b.sc[tid] : -3.0e38f;
            float m = sv;
#pragma unroll
            for (int o = 16; o; o >>= 1) m = fmaxf(m, __shfl_xor_sync(0xffffffffu, m, o));
            if (lane == 0) sm.b.red[warp] = m;
            __syncthreads();
            if (tid == 0) {
                float mm = sm.b.red[0];
#pragma unroll
                for (int w = 1; w < 8; w++) mm = fmaxf(mm, sm.b.red[w]);
                sm.b.misc[0] = mm;
            }
            __syncthreads();
            float ex = (tid < Tq) ? __expf(sv - sm.b.misc[0]) : 0.f;
            float ss = ex;
#pragma unroll
            for (int o = 16; o; o >>= 1) ss += __shfl_xor_sync(0xffffffffu, ss, o);
            if (lane == 0) sm.b.red[warp] = ss;
            __syncthreads();
            if (tid == 0) {
                float tot = 0.f;
#pragma unroll
                for (int w = 0; w < 8; w++) tot += sm.b.red[w];
                sm.b.misc[1] = __fdividef(1.0f, tot);
            }
            if (tid < Tq) sm.b.sc[tid] = ex;
            __syncthreads();
            float invs = sm.b.misc[1];

            // ctx: warp w accumulates 16 t's over all 256 e (8 per lane), fp16 enc
            float a8[8] = {0.f, 0.f, 0.f, 0.f, 0.f, 0.f, 0.f, 0.f};
            const uint4* encb = (const uint4*)(g_encH + (size_t)b * Tq * Eq);
#pragma unroll 4
            for (int i = 0; i < 16; i++) {
                int tt = (warp << 4) + i;
                float wgt = sm.b.sc[tt];
                uint4 ev = __ldcg(encb + (size_t)tt * 32 + lane);
                const __half2* eh = (const __half2*)&ev;
#pragma unroll
                for (int q = 0; q < 4; q++) {
                    float2 f = __half22float2(eh[q]);
                    a8[2 * q]     = fmaf(wgt, f.x, a8[2 * q]);
                    a8[2 * q + 1] = fmaf(wgt, f.y, a8[2 * q + 1]);
                }
            }
#pragma unroll
            for (int j = 0; j < 8; j++) sm.b.ctxp[warp][lane * 8 + j] = a8[j];
            __syncthreads();
            float cv = 0.f;
#pragma unroll
            for (int w = 0; w < 8; w++) cv += sm.b.ctxp[w][tid];
            cv *= invs;
            sm.b.ctx[tid] = cv;

            // y_tilde = ctx . fc_w[0:256] + y_t*fc_w[256] + fc_b
            float ps = cv * fc_w[tid];
#pragma unroll
            for (int o = 16; o; o >>= 1) ps += __shfl_xor_sync(0xffffffffu, ps, o);
            __syncthreads();
            if (lane == 0) sm.b.red[warp] = ps;
            __syncthreads();
            if (tid == 0) {
                float tot = 0.f;
#pragma unroll
                for (int w = 0; w < 8; w++) tot += sm.b.red[w];
                sm.b.misc[2] = tot + yhist[b * Tq + t] * fc_w[256] + fc_b[0];
            }
            __syncthreads();

            // LSTM epilogue (thread = d)
            float yt = sm.b.misc[2];
            int d = tid;
            float gv[4];
#pragma unroll
            for (int g = 0; g < 4; g++) {
                float a = fmaf(yt, w_ih[g * 256 + d], g_bsum[g * 256 + d]);
#pragma unroll
                for (int kq = 0; kq < 8; kq++)
                    a += __ldcg(&g_gp[(size_t)kq * (Bq * G4) + (size_t)b * G4 + g * 256 + d]);
                gv[g] = a;
            }
            float cprev = g_c[b * Dq + d];
            float cn = sigmoid_f(gv[1]) * cprev + sigmoid_f(gv[0]) * tanhf(gv[2]);
            float hn = sigmoid_f(gv[3]) * tanhf(cn);
            g_c[b * Dq + d] = cn;
            g_h[b * Dq + d] = hn;

            if (t == Tq - 1) {
                float q = hn * fcf_w[d] + sm.b.ctx[d] * fcf_w[Dq + d];
#pragma unroll
                for (int o = 16; o; o >>= 1) q += __shfl_xor_sync(0xffffffffu, q, o);
                __syncthreads();
                if (lane == 0) sm.b.red[warp] = q;
                __syncthreads();
                if (tid == 0) {
                    float tot = 0.f;
#pragma unroll
                    for (int w = 0; w < 8; w++) tot += sm.b.red[w];
                    out[b] = tot + fcf_b[0];
                }
            }
        }
        gridbar();
    }
}

__global__ void prep_kernel(const float* __restrict__ w_hh,
                            const float* __restrict__ b_ih,
                            const float* __restrict__ b_hh,
                            const float* __restrict__ enc)
{
    int i = blockIdx.x * blockDim.x + threadIdx.x;   // 262144 threads
    if (i < G4 * Dq) {
        int j = i >> 8, k = i & 255;
        g_whhT[(size_t)k * G4 + j] = w_hh[i];
    }
    if (i < G4) g_bsum[i] = b_ih[i] + b_hh[i];
    if (i < Bq * Dq) { g_h[i] = 0.f; g_c[i] = 0.f; }
    if (i < NLEAF * 32) g_cnt[i] = 0u;
    if (i == 0) { g_master = 0u; g_gen = 0u; }
    for (size_t j = i; j < (size_t)BT * Eq; j += 262144)
        g_encH[j] = __float2half(enc[j]);
}

__global__ void __launch_bounds__(256) pre_gemm_kernel(
        const float* __restrict__ enc, const float* __restrict__ attn_w1,
        const float* __restrict__ attn_b1)
{
    __shared__ SmA sa;
    int mt = blockIdx.x >> 2, nt = blockIdx.x & 3;   // 512 row-tiles x 4 col-tiles
    gemm128x64<__half>(&sa,
        enc + (size_t)mt * 128 * Eq, Eq,
        attn_w1 + (size_t)(2 * Dq) * Eq + nt * 64, Eq,
        g_pre + (size_t)mt * 128 * Eq + nt * 64, Eq, 256,
        attn_b1 + nt * 64);
}

extern "C" void kernel_launch(void* const* d_in, const int* in_sizes, int n_in,
                              void* d_out, int out_size)
{
    const float* enc     = (const float*)d_in[0];
    const float* yhist   = (const float*)d_in[1];
    const float* attn_w1 = (const float*)d_in[2];
    const float* attn_b1 = (const float*)d_in[3];
    const float* attn_w2 = (const float*)d_in[4];
    // d_in[5] = attn_b2: unused (softmax is shift-invariant)
    const float* w_ih    = (const float*)d_in[6];
    const float* w_hh    = (const float*)d_in[7];
    const float* b_ih    = (const float*)d_in[8];
    const float* b_hh    = (const float*)d_in[9];
    const float* fc_w    = (const float*)d_in[10];
    const float* fc_b    = (const float*)d_in[11];
    const float* fcf_w   = (const float*)d_in[12];
    const float* fcf_b   = (const float*)d_in[13];
    float* out = (float*)d_out;

    prep_kernel<<<1024, 256>>>(w_hh, b_ih, b_hh, enc);
    pre_gemm_kernel<<<2048, 256>>>(enc, attn_w1, attn_b1);
    decoder_persist<<<NBLK, 256>>>(yhist, attn_w1, attn_w2, w_ih,
                                   fc_w, fc_b, fcf_w, fcf_b, out);
}